// round 12
// baseline (speedup 1.0000x reference)
#include <cuda_runtime.h>
#include <cstdint>

// Embedding gather, SINGLE fused kernel (bin -> device-wide flag -> stream):
//   x : [16384] int32 token ids        (d_in[0])
//   W : [1024, 50257] f32 row-major    (d_in[1]); embedding of tok = column tok
//   out[s, :] = W[:, x[s]]
//
// Blocks (y==0, x<64) bin tokens by tok>>6 (786 windows of 64 ids = 256B);
// bids 0..63 are wave-1 resident, so all other blocks can safely spin on
// g_binDone. Then every block streams its (bucket, 64-dim chunk): coalesced
// pointer-increment __ldcs of the 256B window into smem, then warp-per-token
// conflict-free LDS + coalesced 128B __stwt rows. Counters self-reset after
// the last chunk-block of each bucket; g_binDone resets only after ALL
// buckets complete (every block has passed the spin by then).

#define TOKENS    50257
#define DIMS      1024
#define NTOK      16384
#define BSHIFT    6
#define WIN       64
#define NBUCKETS  ((TOKENS + WIN - 1) / WIN)   // 786
#define CAP       160
#define DIM_CHUNK 64
#define NCHUNKS   (DIMS / DIM_CHUNK)           // 16
#define TPAD      65
#define NBIN      64                           // binning blocks (bids 0..63)

__device__ int  g_cnt[NBUCKETS];               // zero at load; self-reset
__device__ int  g_done[NBUCKETS];              // per-bucket arrivals; self-reset
__device__ int  g_allDone;                     // buckets completed; self-reset
__device__ volatile int g_binDone;             // bin blocks finished; self-reset
__device__ int2 g_items[NBUCKETS * CAP];       // (tok, original position)

__global__ __launch_bounds__(256, 8)
void k_fused(const int* __restrict__ x,
             const float* __restrict__ W,
             float* __restrict__ out)
{
    __shared__ float tile[DIM_CHUNK * TPAD];
    __shared__ int s_tok[CAP], s_pos[CAP];
    __shared__ int s_n;

    const int b    = blockIdx.x;               // bucket
    const int tid  = threadIdx.x;
    const int lane = tid & 31;
    const int wid  = tid >> 5;

    // ---- Phase 0: binning (blocks y==0, x<64 only; 64*256 = 16384) ----
    if (blockIdx.y == 0 && b < NBIN) {
        int i   = b * 256 + tid;
        int tok = __ldg(&x[i]);
        int bb  = tok >> BSHIFT;
        int s   = atomicAdd(&g_cnt[bb], 1);
        if (s < CAP) g_items[bb * CAP + s] = make_int2(tok, i);
        __threadfence();                       // publish items/counts
        __syncthreads();
        if (tid == 0) atomicAdd((int*)&g_binDone, 1);
    }

    // ---- Device-wide wait: all 64 bin blocks done ----
    if (tid == 0) {
        while (g_binDone < NBIN) __nanosleep(32);
        s_n = min(g_cnt[b], CAP);
    }
    __syncthreads();
    __threadfence();                           // acquire: order gather reads
    const int n = s_n;

    if (n > 0) {
        if (tid < n) {                         // n <= CAP(160) < 256
            int2 e = g_items[b * CAP + tid];
            s_tok[tid] = e.x;
            s_pos[tid] = e.y;
        }

        // ---- Load phase: coalesced streaming (evict-first). ----
        const int w    = b << BSHIFT;
        const int dim0 = blockIdx.y * DIM_CHUNK;
        const int c    = tid & 63;             // lane-consecutive -> 128B LDG
        const int d0   = tid >> 6;             // 0..3

        const float* p  = W + (size_t)(dim0 + d0) * TOKENS + w + c;
        float*       tp = tile + d0 * TPAD + c;

        if (b != NBUCKETS - 1) {
#pragma unroll
            for (int i = 0; i < 16; i++)
                tp[i * (4 * TPAD)] = __ldcs(p + (size_t)i * (4 * TOKENS));
        } else {                               // last window: 17 valid cols
            const bool ok = (c < TOKENS - w);
#pragma unroll
            for (int i = 0; i < 16; i++)
                tp[i * (4 * TPAD)] = ok ? __ldcs(p + (size_t)i * (4 * TOKENS)) : 0.0f;
        }
        __syncthreads();

        // ---- Store phase: warp per token; 2 coalesced 128B WT stores. ----
        for (int t = wid; t < n; t += 8) {
            const int tcol = s_tok[t] - w;
            float* orow = out + (size_t)s_pos[t] * DIMS + dim0;
            __stwt(&orow[lane],      tile[lane * TPAD + tcol]);
            __stwt(&orow[32 + lane], tile[(32 + lane) * TPAD + tcol]);
        }
    }

    // ---- Self-reset chain (safe: g_binDone cleared only after ALL
    //      buckets complete, i.e. after every block passed the spin). ----
    __syncthreads();
    if (tid == 0) {
        if (atomicAdd(&g_done[b], 1) == NCHUNKS - 1) {
            g_cnt[b]  = 0;
            g_done[b] = 0;
            if (atomicAdd(&g_allDone, 1) == NBUCKETS - 1) {
                g_allDone = 0;
                g_binDone = 0;
            }
        }
    }
}

extern "C" void kernel_launch(void* const* d_in, const int* in_sizes, int n_in,
                              void* d_out, int out_size)
{
    const int*   x = (const int*)  d_in[0];
    const float* W = (const float*)d_in[1];
    float*       o = (float*)      d_out;

    dim3 grid(NBUCKETS, NCHUNKS);              // (786, 16)
    k_fused<<<grid, 256>>>(x, W, o);
}

// round 13
// speedup vs baseline: 1.0140x; 1.0140x over previous
#include <cuda_runtime.h>
#include <cstdint>

// Embedding gather as a coalesced STREAM of W, cp.async load phase:
//   x : [16384] int32 token ids        (d_in[0])
//   W : [1024, 50257] f32 row-major    (d_in[1]); embedding of tok = column tok
//   out[s, :] = W[:, x[s]]
//
// k_bin    : bucket tokens by tok>>6 (786 windows of 64 ids = 256B).
// k_gather : block = (bucket, 64-dim chunk). Streams the 256B window for
//            64 dims into smem via cp.async 4B copies (no register dest ->
//            ptxas cannot re-interleave; warp issues all 16 LDGSTS
//            back-to-back = real MLP 16/thread), then warp-per-token
//            conflict-free LDS + coalesced 128B STG rows.

#define TOKENS    50257
#define DIMS      1024
#define NTOK      16384
#define BSHIFT    6
#define WIN       64
#define NBUCKETS  ((TOKENS + WIN - 1) / WIN)   // 786
#define CAP       160
#define DIM_CHUNK 64
#define NCHUNKS   (DIMS / DIM_CHUNK)           // 16
#define TPAD      65

__device__ int  g_cnt[NBUCKETS];               // zero at load; self-reset
__device__ int  g_done[NBUCKETS];              // arrival counters; self-reset
__device__ int2 g_items[NBUCKETS * CAP];       // (tok, original position)

__global__ void k_bin(const int* __restrict__ x)
{
    int i = blockIdx.x * blockDim.x + threadIdx.x;
    if (i < NTOK) {
        int tok = __ldg(&x[i]);
        int b   = tok >> BSHIFT;
        int s   = atomicAdd(&g_cnt[b], 1);
        if (s < CAP) g_items[b * CAP + s] = make_int2(tok, i);
    }
}

// grid (786, 16), 256 threads = 8 warps.
__global__ __launch_bounds__(256, 8)
void k_gather(const float* __restrict__ W, float* __restrict__ out)
{
    __shared__ float tile[DIM_CHUNK * TPAD];   // [dim][token col]
    __shared__ int s_tok[CAP], s_pos[CAP];
    __shared__ int s_n;

    const int b    = blockIdx.x;
    const int tid  = threadIdx.x;
    const int lane = tid & 31;
    const int wid  = tid >> 5;

    if (tid == 0) s_n = min(g_cnt[b], CAP);
    __syncthreads();
    const int n = s_n;

    if (n > 0) {
        if (tid < n) {                          // n <= CAP(160) < 256
            int2 e = g_items[b * CAP + tid];
            s_tok[tid] = e.x;
            s_pos[tid] = e.y;
        }

        // ---- Load phase: 16 back-to-back cp.async 4B copies. ----
        const int w    = b << BSHIFT;
        const int dim0 = blockIdx.y * DIM_CHUNK;
        const int c    = tid & 63;              // lane-consecutive -> 128B/warp
        const int d0   = tid >> 6;              // 0..3

        const float* p = W + (size_t)(dim0 + d0) * TOKENS + w + c;
        uint32_t sa = (uint32_t)__cvta_generic_to_shared(tile + d0 * TPAD + c);

        // src-size operand: 0 for OOB lanes of the last (17-wide) window
        // -> smem is zero-filled, keeping the tile well-defined.
        const int srcsz = (b != NBUCKETS - 1 || c < TOKENS - w) ? 4 : 0;

#pragma unroll
        for (int i = 0; i < 16; i++) {
            asm volatile(
                "cp.async.ca.shared.global [%0], [%1], 4, %2;\n"
                :: "r"(sa + i * (4 * TPAD * 4)),
                   "l"(p + (size_t)i * (4 * TOKENS)),
                   "r"(srcsz));
        }
        asm volatile("cp.async.commit_group;\n" ::: "memory");
        asm volatile("cp.async.wait_group 0;\n" ::: "memory");
        __syncthreads();

        // ---- Store phase: warp per token; 2 coalesced 128B STG rows. ----
        for (int t = wid; t < n; t += 8) {
            const int tcol = s_tok[t] - w;
            float* orow = out + (size_t)s_pos[t] * DIMS + dim0;
            orow[lane]      = tile[lane * TPAD + tcol];
            orow[32 + lane] = tile[(32 + lane) * TPAD + tcol];
        }
    }

    // Self-reset: last chunk-block per bucket restores counters.
    __syncthreads();
    if (tid == 0) {
        if (atomicAdd(&g_done[b], 1) == NCHUNKS - 1) {
            g_cnt[b]  = 0;
            g_done[b] = 0;
        }
    }
}

extern "C" void kernel_launch(void* const* d_in, const int* in_sizes, int n_in,
                              void* d_out, int out_size)
{
    const int*   x = (const int*)  d_in[0];
    const float* W = (const float*)d_in[1];
    float*       o = (float*)      d_out;

    k_bin<<<(NTOK + 255) / 256, 256>>>(x);

    dim3 grid(NBUCKETS, NCHUNKS);              // (786, 16)
    k_gather<<<grid, 256>>>(W, o);
}

// round 14
// speedup vs baseline: 1.1621x; 1.1460x over previous
#include <cuda_runtime.h>
#include <cstdint>

// Embedding gather as a coalesced STREAM of W (R11 structure) + PDL overlap:
//   x : [16384] int32 token ids        (d_in[0])
//   W : [1024, 50257] f32 row-major    (d_in[1]); embedding of tok = column tok
//   out[s, :] = W[:, x[s]]
//
// k_bin    : bucket tokens by tok>>6 (786 windows of 64 ids = 256B);
//            triggers programmatic launch completion early.
// k_gather : launched with ProgrammaticStreamSerialization — blocks spin up
//            while k_bin drains; cudaGridDependencySynchronize() guarantees
//            bin results are visible before any read. Load phase: pointer-
//            increment coalesced LDG.32 into smem; store phase: warp-per-
//            token conflict-free LDS + coalesced 128B STG rows.

#define TOKENS    50257
#define DIMS      1024
#define NTOK      16384
#define BSHIFT    6
#define WIN       64
#define NBUCKETS  ((TOKENS + WIN - 1) / WIN)   // 786
#define CAP       160
#define DIM_CHUNK 64
#define NCHUNKS   (DIMS / DIM_CHUNK)           // 16
#define TPAD      65                           // odd: conflict-free LDS stride

__device__ int  g_cnt[NBUCKETS];               // zero at load; self-reset
__device__ int  g_done[NBUCKETS];              // arrival counters; self-reset
__device__ int2 g_items[NBUCKETS * CAP];       // (tok, original position)

__global__ void k_bin(const int* __restrict__ x)
{
    int i = blockIdx.x * blockDim.x + threadIdx.x;
    if (i < NTOK) {
        int tok = __ldg(&x[i]);
        int b   = tok >> BSHIFT;
        int s   = atomicAdd(&g_cnt[b], 1);
        if (s < CAP) g_items[b * CAP + s] = make_int2(tok, i);
    }
    // Results are flushed by kernel completion; allow the dependent grid
    // to begin launching now.
    cudaTriggerProgrammaticLaunchCompletion();
}

// grid (786, 16), 256 threads = 8 warps.
__global__ __launch_bounds__(256, 8)
void k_gather(const float* __restrict__ W, float* __restrict__ out)
{
    __shared__ float tile[DIM_CHUNK * TPAD];   // [dim][token col]
    __shared__ int s_tok[CAP], s_pos[CAP];
    __shared__ int s_n;

    const int b    = blockIdx.x;
    const int tid  = threadIdx.x;
    const int lane = tid & 31;
    const int wid  = tid >> 5;

    // Wait for k_bin's memory to be visible (PDL dependency).
    cudaGridDependencySynchronize();

    if (tid == 0) s_n = min(g_cnt[b], CAP);
    __syncthreads();
    const int n = s_n;

    if (n > 0) {
        if (tid < n) {                          // n <= CAP(160) < 256
            int2 e = g_items[b * CAP + tid];
            s_tok[tid] = e.x;
            s_pos[tid] = e.y;
        }

        // ---- Load phase: pointer-increment streaming LDG.32. ----
        const int w    = b << BSHIFT;
        const int dim0 = blockIdx.y * DIM_CHUNK;
        const int c    = tid & 63;              // lane-consecutive -> 128B LDG
        const int d0   = tid >> 6;              // 0..3

        const float* p  = W + (size_t)(dim0 + d0) * TOKENS + w + c;
        float*       tp = tile + d0 * TPAD + c;

        if (b != NBUCKETS - 1) {                // full 64-token window
#pragma unroll
            for (int i = 0; i < 16; i++)
                tp[i * (4 * TPAD)] = __ldg(p + (size_t)i * (4 * TOKENS));
        } else {                                // last window: 17 valid cols
            const bool ok = (c < TOKENS - w);
#pragma unroll
            for (int i = 0; i < 16; i++)
                tp[i * (4 * TPAD)] = ok ? __ldg(p + (size_t)i * (4 * TOKENS)) : 0.0f;
        }
        __syncthreads();

        // ---- Store phase: warp per token; 2 coalesced 128B STG rows. ----
        for (int t = wid; t < n; t += 8) {
            const int tcol = s_tok[t] - w;
            float* orow = out + (size_t)s_pos[t] * DIMS + dim0;
            orow[lane]      = tile[lane * TPAD + tcol];
            orow[32 + lane] = tile[(32 + lane) * TPAD + tcol];
        }
    }

    // Self-reset: last chunk-block per bucket restores counters.
    __syncthreads();
    if (tid == 0) {
        if (atomicAdd(&g_done[b], 1) == NCHUNKS - 1) {
            g_cnt[b]  = 0;
            g_done[b] = 0;
        }
    }
}

extern "C" void kernel_launch(void* const* d_in, const int* in_sizes, int n_in,
                              void* d_out, int out_size)
{
    const int*   x = (const int*)  d_in[0];
    const float* W = (const float*)d_in[1];
    float*       o = (float*)      d_out;

    k_bin<<<(NTOK + 255) / 256, 256>>>(x);

    // Dependent launch: k_gather's grid may begin launching while k_bin
    // drains; cudaGridDependencySynchronize() inside enforces visibility.
    cudaLaunchConfig_t cfg = {};
    cfg.gridDim  = dim3(NBUCKETS, NCHUNKS);    // (786, 16)
    cfg.blockDim = dim3(256);
    cfg.stream   = 0;
    cudaLaunchAttribute attr[1];
    attr[0].id = cudaLaunchAttributeProgrammaticStreamSerialization;
    attr[0].val.programmaticStreamSerializationAllowed = 1;
    cfg.attrs    = attr;
    cfg.numAttrs = 1;
    cudaLaunchKernelEx(&cfg, k_gather, W, o);
}

// round 15
// speedup vs baseline: 1.2101x; 1.0412x over previous
#include <cuda_runtime.h>
#include <cstdint>

// Embedding gather as a coalesced STREAM of W + PDL + streaming cache hints:
//   x : [16384] int32 token ids        (d_in[0])
//   W : [1024, 50257] f32 row-major    (d_in[1]); embedding of tok = column tok
//   out[s, :] = W[:, x[s]]
//
// k_bin    : bucket tokens by tok>>6 (786 windows of 64 ids = 256B);
//            PDL-triggers the dependent gather early.
// k_gather : block = (bucket, 64-dim chunk). Load phase: pointer-increment
//            coalesced LDG.32 with evict-first (__ldcs — W is use-once, keep
//            it out of L2). Store phase: warp-per-token conflict-free LDS +
//            coalesced 128B write-through stores (__stwt — no L2
//            write-allocate against the read stream).

#define TOKENS    50257
#define DIMS      1024
#define NTOK      16384
#define BSHIFT    6
#define WIN       64
#define NBUCKETS  ((TOKENS + WIN - 1) / WIN)   // 786
#define CAP       160
#define DIM_CHUNK 64
#define NCHUNKS   (DIMS / DIM_CHUNK)           // 16
#define TPAD      65                           // odd: conflict-free LDS stride

__device__ int  g_cnt[NBUCKETS];               // zero at load; self-reset
__device__ int  g_done[NBUCKETS];              // arrival counters; self-reset
__device__ int2 g_items[NBUCKETS * CAP];       // (tok, original position)

__global__ void k_bin(const int* __restrict__ x)
{
    int i = blockIdx.x * blockDim.x + threadIdx.x;
    if (i < NTOK) {
        int tok = __ldg(&x[i]);
        int b   = tok >> BSHIFT;
        int s   = atomicAdd(&g_cnt[b], 1);
        if (s < CAP) g_items[b * CAP + s] = make_int2(tok, i);
    }
    cudaTriggerProgrammaticLaunchCompletion();
}

// grid (786, 16), 256 threads = 8 warps.
__global__ __launch_bounds__(256, 8)
void k_gather(const float* __restrict__ W, float* __restrict__ out)
{
    __shared__ float tile[DIM_CHUNK * TPAD];   // [dim][token col]
    __shared__ int s_tok[CAP], s_pos[CAP];
    __shared__ int s_n;

    const int b    = blockIdx.x;
    const int tid  = threadIdx.x;
    const int lane = tid & 31;
    const int wid  = tid >> 5;

    cudaGridDependencySynchronize();           // k_bin results visible

    if (tid == 0) s_n = min(g_cnt[b], CAP);
    __syncthreads();
    const int n = s_n;

    if (n > 0) {
        if (tid < n) {                          // n <= CAP(160) < 256
            int2 e = g_items[b * CAP + tid];
            s_tok[tid] = e.x;
            s_pos[tid] = e.y;
        }

        // ---- Load phase: evict-first streaming LDG.32. ----
        const int w    = b << BSHIFT;
        const int dim0 = blockIdx.y * DIM_CHUNK;
        const int c    = tid & 63;              // lane-consecutive -> 128B LDG
        const int d0   = tid >> 6;              // 0..3

        const float* p  = W + (size_t)(dim0 + d0) * TOKENS + w + c;
        float*       tp = tile + d0 * TPAD + c;

        if (b != NBUCKETS - 1) {                // full 64-token window
#pragma unroll
            for (int i = 0; i < 16; i++)
                tp[i * (4 * TPAD)] = __ldcs(p + (size_t)i * (4 * TOKENS));
        } else {                                // last window: 17 valid cols
            const bool ok = (c < TOKENS - w);
#pragma unroll
            for (int i = 0; i < 16; i++)
                tp[i * (4 * TPAD)] = ok ? __ldcs(p + (size_t)i * (4 * TOKENS)) : 0.0f;
        }
        __syncthreads();

        // ---- Store phase: warp per token; 2 coalesced 128B WT stores. ----
        for (int t = wid; t < n; t += 8) {
            const int tcol = s_tok[t] - w;
            float* orow = out + (size_t)s_pos[t] * DIMS + dim0;
            __stwt(&orow[lane],      tile[lane * TPAD + tcol]);
            __stwt(&orow[32 + lane], tile[(32 + lane) * TPAD + tcol]);
        }
    }

    // Self-reset: last chunk-block per bucket restores counters.
    __syncthreads();
    if (tid == 0) {
        if (atomicAdd(&g_done[b], 1) == NCHUNKS - 1) {
            g_cnt[b]  = 0;
            g_done[b] = 0;
        }
    }
}

extern "C" void kernel_launch(void* const* d_in, const int* in_sizes, int n_in,
                              void* d_out, int out_size)
{
    const int*   x = (const int*)  d_in[0];
    const float* W = (const float*)d_in[1];
    float*       o = (float*)      d_out;

    k_bin<<<(NTOK + 255) / 256, 256>>>(x);

    cudaLaunchConfig_t cfg = {};
    cfg.gridDim  = dim3(NBUCKETS, NCHUNKS);    // (786, 16)
    cfg.blockDim = dim3(256);
    cfg.stream   = 0;
    cudaLaunchAttribute attr[1];
    attr[0].id = cudaLaunchAttributeProgrammaticStreamSerialization;
    attr[0].val.programmaticStreamSerializationAllowed = 1;
    cfg.attrs    = attr;
    cfg.numAttrs = 1;
    cudaLaunchKernelEx(&cfg, k_gather, W, o);
}